// round 6
// baseline (speedup 1.0000x reference)
#include <cuda_runtime.h>
#include <cstdint>

// ---------------- problem constants ----------------
#define B      32
#define C0     16
#define H0     128
#define W0     128
#define C1     64
#define NTOK   4096
#define NS     256

// ---------------- scratch ----------------
__device__ __align__(16) float  g_xtok[B * NTOK * C1];      // [b][n][c]
__device__ __align__(16) float  g_xs  [B * NS * C1];        // [b][m][c]
__device__ __align__(16) float2 g_m2h [B * NS];             // {-0.5*|xs|^2, 0}
__device__ __align__(16) float  g_wt2 [C1 * 3 * C1];        // [(k*64+o)*64 + c]
__device__ __align__(16) float  g_y   [B * NS * 3 * C1];    // [pair][k*64+o]
__device__ __align__(16) int4   g_idx [B * NTOK];

__device__ const int SAMP[16] = {0,4,8,13,17,21,25,29,34,38,42,46,50,55,59,63};

#define FMA2(a,x,y) asm("fma.rn.f32x2 %0, %1, %2, %0;" : "+l"(a) : "l"(x), "l"(y))
#define ADD2(a,b)   asm("add.rn.f32x2 %0, %0, %1;" : "+l"(a) : "l"(b))
#define UNPK(lo,hi,a) asm("mov.b64 {%0,%1}, %2;" : "=f"(lo), "=f"(hi) : "l"(a))

// ---------------- kernel 1: pixel_unshuffle (coalesced both sides via smem) ----------
__global__ __launch_bounds__(256) void unshuffle_kernel(const float* __restrict__ x) {
    __shared__ __align__(16) float s[128 * 33];   // s[w][cc], cc=2c+sh
    int b  = blockIdx.x >> 6;
    int h1 = blockIdx.x & 63;
    int t  = threadIdx.x;
    const float* xb = x + (size_t)b * C0 * H0 * W0;
    #pragma unroll
    for (int i = 0; i < 4; i++) {
        int idx = t + 256 * i;
        int r   = idx >> 5;               // 0..31 = 2c+sh
        int w4  = idx & 31;
        int c = r >> 1, sh = r & 1;
        float4 v = *(const float4*)(xb + ((size_t)c * H0 + (2 * h1 + sh)) * W0 + w4 * 4);
        s[(4 * w4 + 0) * 33 + r] = v.x;
        s[(4 * w4 + 1) * 33 + r] = v.y;
        s[(4 * w4 + 2) * 33 + r] = v.z;
        s[(4 * w4 + 3) * 33 + r] = v.w;
    }
    __syncthreads();
    float* dst = g_xtok + ((size_t)b * NTOK + h1 * 64) * C1;
    #pragma unroll
    for (int i = 0; i < 4; i++) {
        int idx = t + 256 * i;
        int w1 = idx >> 4, q = idx & 15;
        int r0 = (2 * w1) * 33, r1 = (2 * w1 + 1) * 33;
        *(float4*)(dst + idx * 4) = make_float4(
            s[r0 + 2 * q],     s[r1 + 2 * q],
            s[r0 + 2 * q + 1], s[r1 + 2 * q + 1]);
    }
}

// ---------------- kernel 2: sampled tokens + packed init {-0.5*m2, 0} ----------------
__global__ void sample_kernel(const float* __restrict__ x) {
    int pair = blockIdx.x;
    int b = pair >> 8, m = pair & 255;
    int h1 = SAMP[m >> 4], w1 = SAMP[m & 15];
    int c1 = threadIdx.x;
    int c = c1 >> 2, sh = (c1 >> 1) & 1, sw = c1 & 1;
    float v = x[((size_t)(b * C0 + c) * H0 + (2 * h1 + sh)) * W0 + (2 * w1 + sw)];
    g_xs[(size_t)pair * C1 + c1] = v;
    __shared__ float red[64];
    red[c1] = v * v;
    __syncthreads();
    if (c1 < 32) {
        float s = red[c1] + red[c1 + 32];
        #pragma unroll
        for (int off = 16; off; off >>= 1)
            s += __shfl_down_sync(0xffffffffu, s, off);
        if (c1 == 0) g_m2h[pair] = make_float2(-0.5f * s, 0.f);
    }
}

// ---------------- kernel 3: weight -> [k][o][c] ----------------
__global__ void wt_kernel(const float* __restrict__ w) {
    int d = blockIdx.x * 256 + threadIdx.x;   // ((k*64+o)*64+c)
    int c = d & 63;
    int ko = d >> 6;
    int o = ko & 63, k = ko >> 6;
    g_wt2[d] = w[o * 192 + c * 3 + k];
}

// ---------------- kernel 4 (launch slot 4 for ncu): scores + branchless top-3 --------
// score s = dot(token, sample) - 0.5*|sample|^2  (rank-equivalent to -d2)
__global__ __launch_bounds__(256, 2) void score_topk_kernel() {
    __shared__ ulonglong2 s_xs[128 * 16];             // 128 samples x 64 floats
    __shared__ unsigned long long s_in[128];          // packed {-0.5*m2, 0}
    const int b   = blockIdx.y;
    const int tok = blockIdx.x * 256 + threadIdx.x;

    unsigned long long tq[32];
    const ulonglong2* tv = (const ulonglong2*)(g_xtok + ((size_t)b * NTOK + tok) * C1);
    #pragma unroll
    for (int j = 0; j < 16; j++) { ulonglong2 v = tv[j]; tq[2 * j] = v.x; tq[2 * j + 1] = v.y; }

    float t0 = -3.4e38f, t1 = -3.4e38f, t2 = -3.4e38f;
    int   i0 = 0, i1 = 0, i2 = 0;

    for (int half = 0; half < 2; half++) {
        __syncthreads();
        const ulonglong2* src = (const ulonglong2*)(g_xs + ((size_t)b * NS + half * 128) * C1);
        #pragma unroll
        for (int j = 0; j < 8; j++)
            s_xs[threadIdx.x + 256 * j] = src[threadIdx.x + 256 * j];
        if (threadIdx.x < 128)
            s_in[threadIdx.x] = ((const unsigned long long*)g_m2h)[b * NS + half * 128 + threadIdx.x];
        __syncthreads();

        #pragma unroll 2
        for (int m = 0; m < 128; m++) {
            unsigned long long a0 = s_in[m];           // {-0.5*m2, 0}
            unsigned long long a1 = 0, a2 = 0, a3 = 0;
            #pragma unroll
            for (int j = 0; j < 8; j++) {
                ulonglong2 qa = s_xs[m * 16 + 2 * j];
                ulonglong2 qb = s_xs[m * 16 + 2 * j + 1];
                FMA2(a0, tq[4 * j + 0], qa.x);
                FMA2(a1, tq[4 * j + 1], qa.y);
                FMA2(a2, tq[4 * j + 2], qb.x);
                FMA2(a3, tq[4 * j + 3], qb.y);
            }
            ADD2(a0, a2); ADD2(a1, a3); ADD2(a0, a1);
            float lo, hi; UNPK(lo, hi, a0);
            float s = lo + hi;
            int gm = half * 128 + m;
            bool g0 = s > t0, g1 = s > t1, g2 = s > t2;
            t2 = g1 ? t1 : (g2 ? s  : t2);
            i2 = g1 ? i1 : (g2 ? gm : i2);
            t1 = g0 ? t0 : (g1 ? s  : t1);
            i1 = g0 ? i0 : (g1 ? gm : i1);
            t0 = g0 ? s  : t0;
            i0 = g0 ? gm : i0;
        }
    }
    g_idx[(size_t)b * NTOK + tok] = make_int4(i0, i1, i2, 0);
}

// ---------------- kernel 5: Y[pair][k*64+o] = sum_c xs[pair][c]*W[c][k][o] (+bias) ----
// 512 blocks x 16 pairs: ~3 resident CTAs/SM (18 warps) to hide LDG/LDS latency.
__global__ __launch_bounds__(192) void y_kernel(const float* __restrict__ bias) {
    int t = threadIdx.x;
    int o = t & 63;
    unsigned long long wq[32];
    const ulonglong2* wp = (const ulonglong2*)(g_wt2 + (size_t)t * 64);
    #pragma unroll
    for (int j = 0; j < 16; j++) { ulonglong2 v = wp[j]; wq[2 * j] = v.x; wq[2 * j + 1] = v.y; }

    __shared__ __align__(16) float s_xs[16 * 64];   // 16 pairs x 64 channels
    const float4* src = (const float4*)(g_xs + (size_t)blockIdx.x * 16 * 64);
    for (int i = t; i < 256; i += 192) ((float4*)s_xs)[i] = src[i];
    __syncthreads();

    float bo = (t < 64) ? bias[o] : 0.f;
    float* yb = g_y + (size_t)blockIdx.x * 16 * 192;
    #pragma unroll 1
    for (int p0 = 0; p0 < 16; p0 += 8) {
        unsigned long long acc[8] = {0,0,0,0,0,0,0,0};
        #pragma unroll
        for (int jj = 0; jj < 16; jj++) {
            #pragma unroll
            for (int p = 0; p < 8; p++) {
                ulonglong2 xq = *(const ulonglong2*)&s_xs[(p0 + p) * 64 + 4 * jj];
                FMA2(acc[p], wq[2 * jj],     xq.x);
                FMA2(acc[p], wq[2 * jj + 1], xq.y);
            }
        }
        #pragma unroll
        for (int p = 0; p < 8; p++) {
            float lo, hi; UNPK(lo, hi, acc[p]);
            yb[(size_t)(p0 + p) * 192 + t] = lo + hi + bo;
        }
    }
}

// ---------------- kernel 6: gather Y by idx, add, pixel_shuffle write ----------------
__global__ __launch_bounds__(256) void gather_out_kernel(float* __restrict__ out) {
    const int b = blockIdx.y;
    const int n = blockIdx.x * 256 + threadIdx.x;
    int4 id = g_idx[(size_t)b * NTOK + n];

    float4 acc[16];
    const float4* y0 = (const float4*)(g_y + ((size_t)(b * NS) + id.x) * 192);
    #pragma unroll
    for (int j = 0; j < 16; j++) acc[j] = y0[j];
    const float4* y1 = (const float4*)(g_y + ((size_t)(b * NS) + id.y) * 192 + 64);
    #pragma unroll
    for (int j = 0; j < 16; j++) {
        float4 v = y1[j];
        acc[j].x += v.x; acc[j].y += v.y; acc[j].z += v.z; acc[j].w += v.w;
    }
    const float4* y2 = (const float4*)(g_y + ((size_t)(b * NS) + id.z) * 192 + 128);
    #pragma unroll
    for (int j = 0; j < 16; j++) {
        float4 v = y2[j];
        acc[j].x += v.x; acc[j].y += v.y; acc[j].z += v.z; acc[j].w += v.w;
    }

    int h1 = n >> 6, w1 = n & 63;
    float* ob = out + (size_t)b * C0 * (H0 * W0);
    #pragma unroll
    for (int co = 0; co < 16; co++) {
        *(float2*)(ob + co * (H0 * W0) + (2 * h1)     * W0 + 2 * w1) = make_float2(acc[co].x, acc[co].y);
        *(float2*)(ob + co * (H0 * W0) + (2 * h1 + 1) * W0 + 2 * w1) = make_float2(acc[co].z, acc[co].w);
    }
}

// ---------------- launcher (score in slot 4 so ncu captures it) ----------------
extern "C" void kernel_launch(void* const* d_in, const int* in_sizes, int n_in,
                              void* d_out, int out_size) {
    const float* x    = (const float*)d_in[0];
    const float* w    = (const float*)d_in[1];
    const float* bias = (const float*)d_in[2];
    float* out = (float*)d_out;

    unshuffle_kernel<<<B * 64, 256>>>(x);
    sample_kernel<<<B * NS, 64>>>(x);
    wt_kernel<<<48, 256>>>(w);
    score_topk_kernel<<<dim3(NTOK / 256, B), 256>>>();
    y_kernel<<<B * NS / 16, 192>>>(bias);
    gather_out_kernel<<<dim3(NTOK / 256, B), 256>>>(out);
}

// round 7
// speedup vs baseline: 1.0350x; 1.0350x over previous
#include <cuda_runtime.h>
#include <cstdint>

// ---------------- problem constants ----------------
#define B      32
#define C0     16
#define H0     128
#define W0     128
#define C1     64
#define NTOK   4096
#define NS     256

// ---------------- scratch ----------------
__device__ __align__(16) float  g_xtok[B * NTOK * C1];      // [b][n][c]
__device__ __align__(16) float  g_xs  [B * NS * C1];        // [b][m][c]
__device__ __align__(16) float2 g_m2h [B * NS];             // {-0.5*|xs|^2, 0}
__device__ __align__(16) float  g_wt2 [C1 * 3 * C1];        // [(k*64+o)*64 + c]
__device__ __align__(16) float  g_y   [B * NS * 3 * C1];    // [pair][k*64+o]
__device__ __align__(16) int4   g_idx [B * NTOK];

__device__ const int SAMP[16] = {0,4,8,13,17,21,25,29,34,38,42,46,50,55,59,63};

#define FMA2(a,x,y) asm("fma.rn.f32x2 %0, %1, %2, %0;" : "+l"(a) : "l"(x), "l"(y))
#define ADD2(a,b)   asm("add.rn.f32x2 %0, %0, %1;" : "+l"(a) : "l"(b))
#define UNPK(lo,hi,a) asm("mov.b64 {%0,%1}, %2;" : "=f"(lo), "=f"(hi) : "l"(a))

// ---------------- kernel 1: pixel_unshuffle (coalesced both sides via smem) ----------
__global__ __launch_bounds__(256) void unshuffle_kernel(const float* __restrict__ x) {
    __shared__ __align__(16) float s[128 * 33];   // s[w][cc], cc=2c+sh
    int b  = blockIdx.x >> 6;
    int h1 = blockIdx.x & 63;
    int t  = threadIdx.x;
    const float* xb = x + (size_t)b * C0 * H0 * W0;
    #pragma unroll
    for (int i = 0; i < 4; i++) {
        int idx = t + 256 * i;
        int r   = idx >> 5;               // 0..31 = 2c+sh
        int w4  = idx & 31;
        int c = r >> 1, sh = r & 1;
        float4 v = *(const float4*)(xb + ((size_t)c * H0 + (2 * h1 + sh)) * W0 + w4 * 4);
        s[(4 * w4 + 0) * 33 + r] = v.x;
        s[(4 * w4 + 1) * 33 + r] = v.y;
        s[(4 * w4 + 2) * 33 + r] = v.z;
        s[(4 * w4 + 3) * 33 + r] = v.w;
    }
    __syncthreads();
    float* dst = g_xtok + ((size_t)b * NTOK + h1 * 64) * C1;
    #pragma unroll
    for (int i = 0; i < 4; i++) {
        int idx = t + 256 * i;
        int w1 = idx >> 4, q = idx & 15;
        int r0 = (2 * w1) * 33, r1 = (2 * w1 + 1) * 33;
        *(float4*)(dst + idx * 4) = make_float4(
            s[r0 + 2 * q],     s[r1 + 2 * q],
            s[r0 + 2 * q + 1], s[r1 + 2 * q + 1]);
    }
}

// ---------------- kernel 2: sampled tokens + packed init {-0.5*m2, 0} ----------------
__global__ void sample_kernel(const float* __restrict__ x) {
    int pair = blockIdx.x;
    int b = pair >> 8, m = pair & 255;
    int h1 = SAMP[m >> 4], w1 = SAMP[m & 15];
    int c1 = threadIdx.x;
    int c = c1 >> 2, sh = (c1 >> 1) & 1, sw = c1 & 1;
    float v = x[((size_t)(b * C0 + c) * H0 + (2 * h1 + sh)) * W0 + (2 * w1 + sw)];
    g_xs[(size_t)pair * C1 + c1] = v;
    __shared__ float red[64];
    red[c1] = v * v;
    __syncthreads();
    if (c1 < 32) {
        float s = red[c1] + red[c1 + 32];
        #pragma unroll
        for (int off = 16; off; off >>= 1)
            s += __shfl_down_sync(0xffffffffu, s, off);
        if (c1 == 0) g_m2h[pair] = make_float2(-0.5f * s, 0.f);
    }
}

// ---------------- kernel 3: weight -> [k][o][c] ----------------
__global__ void wt_kernel(const float* __restrict__ w) {
    int d = blockIdx.x * 256 + threadIdx.x;   // ((k*64+o)*64+c)
    int c = d & 63;
    int ko = d >> 6;
    int o = ko & 63, k = ko >> 6;
    g_wt2[d] = w[o * 192 + c * 3 + k];
}

// ---------------- kernel 4 (slot 4 for ncu): scores + top-3, 2 TOKENS PER THREAD -----
// Each 8-LDS.128 sample fetch now feeds 64 FFMA2 (was 32): smem traffic halved.
__global__ __launch_bounds__(128, 2) void score_topk_kernel() {
    __shared__ ulonglong2 s_xs[128 * 16];             // 128 samples x 64 floats (32 KB)
    __shared__ unsigned long long s_in[128];          // packed {-0.5*m2, 0}
    const int b    = blockIdx.y;
    const int tok0 = blockIdx.x * 256 + threadIdx.x;  // tokens [base+t, base+128+t]
    const int tok1 = tok0 + 128;

    unsigned long long tqA[32], tqB[32];
    {
        const ulonglong2* tv = (const ulonglong2*)(g_xtok + ((size_t)b * NTOK + tok0) * C1);
        #pragma unroll
        for (int j = 0; j < 16; j++) { ulonglong2 v = tv[j]; tqA[2 * j] = v.x; tqA[2 * j + 1] = v.y; }
        const ulonglong2* tw = (const ulonglong2*)(g_xtok + ((size_t)b * NTOK + tok1) * C1);
        #pragma unroll
        for (int j = 0; j < 16; j++) { ulonglong2 v = tw[j]; tqB[2 * j] = v.x; tqB[2 * j + 1] = v.y; }
    }

    float tA0 = -3.4e38f, tA1 = -3.4e38f, tA2 = -3.4e38f;
    float tB0 = -3.4e38f, tB1 = -3.4e38f, tB2 = -3.4e38f;
    int   iA0 = 0, iA1 = 0, iA2 = 0, iB0 = 0, iB1 = 0, iB2 = 0;

    for (int half = 0; half < 2; half++) {
        __syncthreads();
        const ulonglong2* src = (const ulonglong2*)(g_xs + ((size_t)b * NS + half * 128) * C1);
        #pragma unroll
        for (int j = 0; j < 16; j++)
            s_xs[threadIdx.x + 128 * j] = src[threadIdx.x + 128 * j];
        s_in[threadIdx.x] = ((const unsigned long long*)g_m2h)[b * NS + half * 128 + threadIdx.x];
        __syncthreads();

        #pragma unroll 1
        for (int m = 0; m < 128; m++) {
            unsigned long long init = s_in[m];         // {-0.5*m2, 0}
            unsigned long long a0 = init, a1 = 0, a2 = 0, a3 = 0;
            unsigned long long c0 = init, c1 = 0, c2 = 0, c3 = 0;
            #pragma unroll
            for (int j = 0; j < 8; j++) {
                ulonglong2 qa = s_xs[m * 16 + 2 * j];
                ulonglong2 qb = s_xs[m * 16 + 2 * j + 1];
                FMA2(a0, tqA[4 * j + 0], qa.x);
                FMA2(a1, tqA[4 * j + 1], qa.y);
                FMA2(a2, tqA[4 * j + 2], qb.x);
                FMA2(a3, tqA[4 * j + 3], qb.y);
                FMA2(c0, tqB[4 * j + 0], qa.x);
                FMA2(c1, tqB[4 * j + 1], qa.y);
                FMA2(c2, tqB[4 * j + 2], qb.x);
                FMA2(c3, tqB[4 * j + 3], qb.y);
            }
            ADD2(a0, a2); ADD2(a1, a3); ADD2(a0, a1);
            ADD2(c0, c2); ADD2(c1, c3); ADD2(c0, c1);
            float lo, hi; UNPK(lo, hi, a0);
            float sA = lo + hi;
            UNPK(lo, hi, c0);
            float sB = lo + hi;
            int gm = half * 128 + m;
            // branchless top-3 (strict > keeps earlier index on ties = stable top_k)
            bool g0 = sA > tA0, g1 = sA > tA1, g2 = sA > tA2;
            tA2 = g1 ? tA1 : (g2 ? sA : tA2);  iA2 = g1 ? iA1 : (g2 ? gm : iA2);
            tA1 = g0 ? tA0 : (g1 ? sA : tA1);  iA1 = g0 ? iA0 : (g1 ? gm : iA1);
            tA0 = g0 ? sA  : tA0;              iA0 = g0 ? gm  : iA0;
            bool h0 = sB > tB0, h1 = sB > tB1, h2 = sB > tB2;
            tB2 = h1 ? tB1 : (h2 ? sB : tB2);  iB2 = h1 ? iB1 : (h2 ? gm : iB2);
            tB1 = h0 ? tB0 : (h1 ? sB : tB1);  iB1 = h0 ? iB0 : (h1 ? gm : iB1);
            tB0 = h0 ? sB  : tB0;              iB0 = h0 ? gm  : iB0;
        }
    }
    g_idx[(size_t)b * NTOK + tok0] = make_int4(iA0, iA1, iA2, 0);
    g_idx[(size_t)b * NTOK + tok1] = make_int4(iB0, iB1, iB2, 0);
}

// ---------------- kernel 5: Y[pair][k*64+o] (+bias), 256 blocks x 32 pairs ----------
__global__ __launch_bounds__(192) void y_kernel(const float* __restrict__ bias) {
    int t = threadIdx.x;
    int o = t & 63;
    unsigned long long wq[32];
    const ulonglong2* wp = (const ulonglong2*)(g_wt2 + (size_t)t * 64);
    #pragma unroll
    for (int j = 0; j < 16; j++) { ulonglong2 v = wp[j]; wq[2 * j] = v.x; wq[2 * j + 1] = v.y; }

    __shared__ __align__(16) float s_xs[32 * 64];   // 32 pairs x 64 channels
    const float4* src = (const float4*)(g_xs + (size_t)blockIdx.x * 32 * 64);
    for (int i = t; i < 512; i += 192) ((float4*)s_xs)[i] = src[i];
    __syncthreads();

    float bo = (t < 64) ? bias[o] : 0.f;
    float* yb = g_y + (size_t)blockIdx.x * 32 * 192;
    #pragma unroll 1
    for (int p0 = 0; p0 < 32; p0 += 8) {
        unsigned long long acc[8] = {0,0,0,0,0,0,0,0};
        #pragma unroll
        for (int jj = 0; jj < 16; jj++) {
            #pragma unroll
            for (int p = 0; p < 8; p++) {
                ulonglong2 xq = *(const ulonglong2*)&s_xs[(p0 + p) * 64 + 4 * jj];
                FMA2(acc[p], wq[2 * jj],     xq.x);
                FMA2(acc[p], wq[2 * jj + 1], xq.y);
            }
        }
        #pragma unroll
        for (int p = 0; p < 8; p++) {
            float lo, hi; UNPK(lo, hi, acc[p]);
            yb[(size_t)(p0 + p) * 192 + t] = lo + hi + bo;
        }
    }
}

// ---------------- kernel 6: gather Y by idx, add, pixel_shuffle write ----------------
__global__ __launch_bounds__(256) void gather_out_kernel(float* __restrict__ out) {
    const int b = blockIdx.y;
    const int n = blockIdx.x * 256 + threadIdx.x;
    int4 id = g_idx[(size_t)b * NTOK + n];

    float4 acc[16];
    const float4* y0 = (const float4*)(g_y + ((size_t)(b * NS) + id.x) * 192);
    #pragma unroll
    for (int j = 0; j < 16; j++) acc[j] = y0[j];
    const float4* y1 = (const float4*)(g_y + ((size_t)(b * NS) + id.y) * 192 + 64);
    #pragma unroll
    for (int j = 0; j < 16; j++) {
        float4 v = y1[j];
        acc[j].x += v.x; acc[j].y += v.y; acc[j].z += v.z; acc[j].w += v.w;
    }
    const float4* y2 = (const float4*)(g_y + ((size_t)(b * NS) + id.z) * 192 + 128);
    #pragma unroll
    for (int j = 0; j < 16; j++) {
        float4 v = y2[j];
        acc[j].x += v.x; acc[j].y += v.y; acc[j].z += v.z; acc[j].w += v.w;
    }

    int h1 = n >> 6, w1 = n & 63;
    float* ob = out + (size_t)b * C0 * (H0 * W0);
    #pragma unroll
    for (int co = 0; co < 16; co++) {
        *(float2*)(ob + co * (H0 * W0) + (2 * h1)     * W0 + 2 * w1) = make_float2(acc[co].x, acc[co].y);
        *(float2*)(ob + co * (H0 * W0) + (2 * h1 + 1) * W0 + 2 * w1) = make_float2(acc[co].z, acc[co].w);
    }
}

// ---------------- launcher (score in slot 4 so ncu captures it) ----------------
extern "C" void kernel_launch(void* const* d_in, const int* in_sizes, int n_in,
                              void* d_out, int out_size) {
    const float* x    = (const float*)d_in[0];
    const float* w    = (const float*)d_in[1];
    const float* bias = (const float*)d_in[2];
    float* out = (float*)d_out;

    unshuffle_kernel<<<B * 64, 256>>>(x);
    sample_kernel<<<B * NS, 64>>>(x);
    wt_kernel<<<48, 256>>>(w);
    score_topk_kernel<<<dim3(NTOK / 256, B), 128>>>();
    y_kernel<<<B * NS / 32, 192>>>(bias);
    gather_out_kernel<<<dim3(NTOK / 256, B), 256>>>(out);
}